// round 16
// baseline (speedup 1.0000x reference)
#include <cuda_runtime.h>
#include <cuda_bf16.h>
#include <math.h>

#define NLAYERS 12
#define DMODEL  256
#define DINNER  512
#define DTRANK  16
#define DSTATE  16
#define INDIM   230
#define BATCH   4096
#define ROWS    16
#define NTHREADS 512

#define KT1 16    // 256/16 k-tiles, GEMM1
#define NT1 128   // 1024/8 n-tiles, GEMM1
#define KT3 32    // 512/16 k-tiles, GEMM3
#define NT3 32    // 256/8  n-tiles, GEMM3
#define KT2 32    // 512/16 k-tiles, GEMM2
#define NT2 6     // 48/8   n-tiles, GEMM2
#define NT4 64    // 512/8  n-tiles, dt-GEMM (K=16)
// packed single-term weights:
//   g_W1: uint4 per (kt, nt-pair): .xy = nt even, .zw = nt odd
//   g_W3: uint4 per (kt-pair, nt): .xy = kt even, .zw = kt odd
#define NG1 (NLAYERS*KT1*(NT1/2)*32)   // 393216 uint4
#define NG3 (NLAYERS*(KT3/2)*NT3*32)   // 196608 uint4
#define NG2 (NLAYERS*KT2*NT2*32)       // 73728 uint2
#define NG4 (NLAYERS*NT4*32)           // 24576 uint2
#define NCP (NLAYERS*256)              // col pairs for aux packs

__device__ uint4  g_W1[NG1];
__device__ uint4  g_W3[NG3];
__device__ uint2  g_W2h[NG2];
__device__ uint2  g_W4h[NG4];
__device__ float4 g_cvb[NCP];   // (convw3[c], convb[c], convw3[c+1], convb[c+1])
__device__ float4 g_dbd[NCP];   // (dtb[c], D[c], dtb[c+1], D[c+1])

// ---------------------------------------------------------------------------
union F2 { float2 f; unsigned long long u; };
__device__ __forceinline__ void ffma2(F2 &d, const F2 a, const F2 b) {
    asm("fma.rn.f32x2 %0, %1, %2, %0;" : "+l"(d.u) : "l"(a.u), "l"(b.u));
}
__device__ __forceinline__ F2 bcast2(float v) { F2 r; r.f = make_float2(v, v); return r; }

__device__ __forceinline__ float silu_f(float v) {
    return v * (1.0f / (1.0f + __expf(-v)));
}
__device__ __forceinline__ float softplus_f(float v) {
    return (v > 20.0f) ? v : log1pf(__expf(v));
}

__device__ __forceinline__ unsigned pack_bf2(float x, float y) {
    __nv_bfloat162 h = __floats2bfloat162_rn(x, y);
    return *reinterpret_cast<unsigned*>(&h);
}
__device__ __forceinline__ float2 bf2f2(unsigned p) {
    __nv_bfloat162 b = *reinterpret_cast<__nv_bfloat162*>(&p);
    return __bfloat1622float2(b);
}

__device__ __forceinline__ void mma_bf16(float (&d)[4], const unsigned (&a)[4],
                                         unsigned b0, unsigned b1) {
    asm volatile(
        "mma.sync.aligned.m16n8k16.row.col.f32.bf16.bf16.f32 "
        "{%0,%1,%2,%3}, {%4,%5,%6,%7}, {%8,%9}, {%0,%1,%2,%3};"
        : "+f"(d[0]), "+f"(d[1]), "+f"(d[2]), "+f"(d[3])
        : "r"(a[0]), "r"(a[1]), "r"(a[2]), "r"(a[3]), "r"(b0), "r"(b1));
}

// ---------------------------------------------------------------------------
// prep: repack weights into mma B-fragment order (single-term bf16, packed)
// plus interleaved epilogue constants.
// ---------------------------------------------------------------------------
extern "C" __global__ void prep_kernel(const float* __restrict__ in_proj_w,
                                       const float* __restrict__ out_proj_w,
                                       const float* __restrict__ x_proj_w,
                                       const float* __restrict__ dt_proj_w,
                                       const float* __restrict__ conv_w,
                                       const float* __restrict__ conv_b,
                                       const float* __restrict__ dt_proj_b,
                                       const float* __restrict__ Dvec)
{
    int gid = blockIdx.x * blockDim.x + threadIdx.x;

    if (gid < NG1) {
        int idx = gid;
        int lane = idx & 31; int rest = idx >> 5;
        int ntp = rest % (NT1 / 2); rest /= (NT1 / 2);
        int kt = rest % KT1; int l = rest / KT1;
        int n0 = (2 * ntp) * 8 + (lane >> 2);
        int n1 = n0 + 8;
        int k0 = kt * 16 + (lane & 3) * 2;
        const float* W = in_proj_w + (size_t)l * DMODEL * 1024;
        g_W1[idx] = make_uint4(
            pack_bf2(W[(size_t)k0 * 1024 + n0],       W[(size_t)(k0 + 1) * 1024 + n0]),
            pack_bf2(W[(size_t)(k0 + 8) * 1024 + n0], W[(size_t)(k0 + 9) * 1024 + n0]),
            pack_bf2(W[(size_t)k0 * 1024 + n1],       W[(size_t)(k0 + 1) * 1024 + n1]),
            pack_bf2(W[(size_t)(k0 + 8) * 1024 + n1], W[(size_t)(k0 + 9) * 1024 + n1]));
    } else if (gid < NG1 + NG3) {
        int idx = gid - NG1;
        int lane = idx & 31; int rest = idx >> 5;
        int nt = rest % NT3; rest /= NT3;
        int ktp = rest % (KT3 / 2); int l = rest / (KT3 / 2);
        int n  = nt * 8 + (lane >> 2);
        int ka = (2 * ktp) * 16 + (lane & 3) * 2;
        int kb = ka + 16;
        const float* W = out_proj_w + (size_t)l * DINNER * DMODEL;
        g_W3[idx] = make_uint4(
            pack_bf2(W[(size_t)ka * DMODEL + n],       W[(size_t)(ka + 1) * DMODEL + n]),
            pack_bf2(W[(size_t)(ka + 8) * DMODEL + n], W[(size_t)(ka + 9) * DMODEL + n]),
            pack_bf2(W[(size_t)kb * DMODEL + n],       W[(size_t)(kb + 1) * DMODEL + n]),
            pack_bf2(W[(size_t)(kb + 8) * DMODEL + n], W[(size_t)(kb + 9) * DMODEL + n]));
    } else if (gid < NG1 + NG3 + NG2) {
        int idx = gid - NG1 - NG3;
        int lane = idx & 31; int rest = idx >> 5;
        int nt = rest % NT2; rest /= NT2;
        int kt = rest % KT2; int l = rest / KT2;
        int n  = nt * 8 + (lane >> 2);
        int k0 = kt * 16 + (lane & 3) * 2;
        const float* W = x_proj_w + (size_t)l * DINNER * 48;
        g_W2h[idx] = make_uint2(
            pack_bf2(W[(size_t)k0 * 48 + n],       W[(size_t)(k0 + 1) * 48 + n]),
            pack_bf2(W[(size_t)(k0 + 8) * 48 + n], W[(size_t)(k0 + 9) * 48 + n]));
    } else if (gid < NG1 + NG3 + NG2 + NG4) {
        int idx = gid - NG1 - NG3 - NG2;
        int lane = idx & 31; int rest = idx >> 5;
        int nt = rest % NT4; int l = rest / NT4;
        int n  = nt * 8 + (lane >> 2);
        int k0 = (lane & 3) * 2;
        const float* W = dt_proj_w + (size_t)l * DTRANK * DINNER;
        g_W4h[idx] = make_uint2(
            pack_bf2(W[(size_t)k0 * DINNER + n],       W[(size_t)(k0 + 1) * DINNER + n]),
            pack_bf2(W[(size_t)(k0 + 8) * DINNER + n], W[(size_t)(k0 + 9) * DINNER + n]));
    } else if (gid < NG1 + NG3 + NG2 + NG4 + NCP) {
        int idx = gid - NG1 - NG3 - NG2 - NG4;
        int cp = idx & 255, l = idx >> 8;
        int c = cp * 2;
        g_cvb[idx] = make_float4(conv_w[((size_t)l * DINNER + c) * 4 + 3],
                                 conv_b[(size_t)l * DINNER + c],
                                 conv_w[((size_t)l * DINNER + c + 1) * 4 + 3],
                                 conv_b[(size_t)l * DINNER + c + 1]);
    } else if (gid < NG1 + NG3 + NG2 + NG4 + 2 * NCP) {
        int idx = gid - NG1 - NG3 - NG2 - NG4 - NCP;
        int cp = idx & 255, l = idx >> 8;
        int c = cp * 2;
        g_dbd[idx] = make_float4(dt_proj_b[(size_t)l * DINNER + c],
                                 Dvec[(size_t)l * DINNER + c],
                                 dt_proj_b[(size_t)l * DINNER + c + 1],
                                 Dvec[(size_t)l * DINNER + c + 1]);
    }
}

// ---------------------------------------------------------------------------
// main: one block = 16 batch rows, 512 threads, 2 CTAs/SM.
// 4 phases/layer with distance-1 double-buffered weight prefetch everywhere.
// THREE exact exits (h==0 fixed point; wall = max over CTAs):
//   (0) xc == 0 after GEMM1 -> skips G2+gate+G3 on the exit layer
//   (a) y  == 0 after gating -> skips G3
//   (b) h' == 0 after GEMM3
// A-frag layout: (row r, col pair c): kt=c/16, lane=(r%8)*4+((c%8)/2),
//   reg=(r/8)+2*((c%16)/8)
// SMEM (words): dbl[0,768) | u32 at 768: dtH 128 | hH 2048 | xH 4096 | zH 4096
// total 11136 words = 44544 B/CTA
// ---------------------------------------------------------------------------
extern "C" __global__ void __launch_bounds__(NTHREADS, 2)
mamba_icl_kernel(const float* __restrict__ x,
                 const float* __restrict__ Wi,
                 const float* __restrict__ bi,
                 const float* __restrict__ Wo,
                 const float* __restrict__ bo,
                 float* __restrict__ out)
{
    extern __shared__ float sm[];
    float*    sh_dbl = sm;                  // 16x48
    unsigned* fr_    = (unsigned*)(sm + 768);
    unsigned* dtH = fr_;                  // 128
    unsigned* hH  = fr_ + 128;            // 2048
    unsigned* xH  = fr_ + 2176;           // 4096
    unsigned* zH  = fr_ + 6272;           // 4096

    const int t    = threadIdx.x;
    const int row0 = blockIdx.x * ROWS;
    const int wid  = t >> 5;          // 0..15
    const int lane = t & 31;
    const int fr   = lane >> 2;
    const int fc   = (lane & 3) * 2;

    // ---- stage x into scratch aliasing the xc-frag region ----
    float* sh_x = (float*)xH;   // 3680 floats < 4096-word xH region
    for (int idx = t; idx < ROWS * INDIM; idx += NTHREADS) {
        int r = idx / INDIM, c = idx - r * INDIM;
        sh_x[r * INDIM + c] = x[(size_t)(row0 + r) * INDIM + c];
    }
    __syncthreads();

    // ---- input projection -> h-frags (fp32 FFMA2, one-time) ----
    {
        const int tx = t & 127;     // col pair
        const int ty = t >> 7;      // 0..3 -> 4 rows each
        F2 acc[4];
        #pragma unroll
        for (int i = 0; i < 4; i++) acc[i].f = make_float2(0.f, 0.f);
        const int rbase = ty * 4;
        #pragma unroll 2
        for (int k0 = 0; k0 < INDIM; k0 += 2) {
            F2 w0; w0.f = *(const float2*)(Wi + (size_t)k0 * DMODEL + tx * 2);
            F2 w1; w1.f = *(const float2*)(Wi + (size_t)(k0 + 1) * DMODEL + tx * 2);
            #pragma unroll
            for (int i = 0; i < 4; i++) {
                float2 a2 = *(const float2*)(sh_x + (rbase + i) * INDIM + k0);
                ffma2(acc[i], bcast2(a2.x), w0);
                ffma2(acc[i], bcast2(a2.y), w1);
            }
        }
        __syncthreads();   // all reads of sh_x done before frag region reuse
        float2 bv = *(const float2*)(bi + tx * 2);
        const int kt = tx >> 3;
        #pragma unroll
        for (int i = 0; i < 4; i++) {
            int row = rbase + i;
            unsigned hh = pack_bf2(acc[i].f.x + bv.x, acc[i].f.y + bv.y);
            int idx = (kt * 32 + (row & 7) * 4 + (tx & 3)) * 4
                      + (row >> 3) + 2 * ((tx >> 2) & 1);
            hH[idx] = hh;
        }
    }
    __syncthreads();

    for (int l = 0; l < NLAYERS; l++) {
        // ==== GEMM1: [16,256]@[256,1024]; 2 chunks x 4nt, W double-buffer ==
        unsigned xc_nonzero = 0u;
        #pragma unroll
        for (int ch = 0; ch < 2; ch++) {
            float acc[4][4];   // 16 regs
            #pragma unroll
            for (int j = 0; j < 4; j++)
                #pragma unroll
                for (int k = 0; k < 4; k++) acc[j][k] = 0.f;

            const int ntp0 = wid * 4 + ch * 2;   // pairs {ntp0, ntp0+1} = 4 nts
            const uint4* bwbase = g_W1 + ((size_t)l * KT1 * (NT1 / 2) + ntp0) * 32 + lane;
            uint4 nW0 = bwbase[0];
            uint4 nW1 = bwbase[32];
            for (int kt = 0; kt < KT1; kt++) {
                uint4 W0 = nW0, W1 = nW1;
                const int kn = (kt + 1) & (KT1 - 1);   // wraps; extra loads discarded
                nW0 = bwbase[(size_t)kn * (NT1 / 2) * 32];
                nW1 = bwbase[(size_t)kn * (NT1 / 2) * 32 + 32];
                unsigned ah[4];
                *(uint4*)ah = *(const uint4*)&hH[(kt * 32 + lane) * 4];
                mma_bf16(acc[0], ah, W0.x, W0.y);
                mma_bf16(acc[1], ah, W0.z, W0.w);
                mma_bf16(acc[2], ah, W1.x, W1.y);
                mma_bf16(acc[3], ah, W1.z, W1.w);
            }
            // epilogue: warps 0-7 -> xc frags (conv+silu); 8-15 -> z frags
            if (wid < 8) {
                #pragma unroll
                for (int j = 0; j < 4; j++) {
                    int nt = (wid * 4 + ch * 2) * 2 + j;
                    int c  = nt * 8 + fc;
                    float4 cv = g_cvb[l * 256 + (c >> 1)];
                    float v00 = silu_f(acc[j][0] * cv.x + cv.y);
                    float v01 = silu_f(acc[j][1] * cv.z + cv.w);
                    float v10 = silu_f(acc[j][2] * cv.x + cv.y);
                    float v11 = silu_f(acc[j][3] * cv.z + cv.w);
                    unsigned p0 = pack_bf2(v00, v01);
                    unsigned p1 = pack_bf2(v10, v11);
                    int idx = ((c >> 4) * 32 + lane) * 4 + 2 * (nt & 1);
                    *(uint2*)&xH[idx] = make_uint2(p0, p1);
                    xc_nonzero |= (p0 & 0x7FFF7FFFu) | (p1 & 0x7FFF7FFFu);
                }
            } else {
                #pragma unroll
                for (int j = 0; j < 4; j++) {
                    int nt = ((wid - 8) * 4 + ch * 2) * 2 + j;   // z tile 0..63
                    int c  = nt * 8 + fc;
                    int idx = ((c >> 4) * 32 + lane) * 4 + 2 * (nt & 1);
                    *(uint2*)&zH[idx] = make_uint2(
                        pack_bf2(silu_f(acc[j][0]), silu_f(acc[j][1])),
                        pack_bf2(silu_f(acc[j][2]), silu_f(acc[j][3])));
                }
            }
        }
        // Exit (0): xc == 0 (bf16) => y = xc*(...)*(...) = 0 => h' = 0.
        if (!__syncthreads_or(xc_nonzero != 0u)) {
            for (int i = t; i < 2048; i += NTHREADS) hH[i] = 0u;
            __syncthreads();
            break;
        }

        // ==== GEMM2: dbl = xc @ x_proj, 6 warps full-K, W prefetch ========
        // warps 0,1 own dt columns 0-15: their D-fragments ARE the dt-GEMM
        // A-fragments -> pack dtH directly, no extra phase.
        if (wid < 6) {
            float d[4] = {0.f, 0.f, 0.f, 0.f};
            const uint2* w2base = g_W2h + ((size_t)l * KT2 * NT2 + wid) * 32 + lane;
            uint2 nW = w2base[0];
            for (int kt = 0; kt < KT2; kt++) {
                uint2 W = nW;
                const int kn = (kt + 1) & (KT2 - 1);
                nW = w2base[(size_t)kn * NT2 * 32];
                unsigned ahi[4];
                *(uint4*)ahi = *(const uint4*)&xH[(kt * 32 + lane) * 4];
                mma_bf16(d, ahi, W.x, W.y);
            }
            if (wid < 2) {
                dtH[lane * 4 + 2 * wid]     = pack_bf2(d[0], d[1]);
                dtH[lane * 4 + 2 * wid + 1] = pack_bf2(d[2], d[3]);
            } else {
                int c = wid * 8 + fc;
                *(float2*)&sh_dbl[fr * 48 + c]       = make_float2(d[0], d[1]);
                *(float2*)&sh_dbl[(fr + 8) * 48 + c] = make_float2(d[2], d[3]);
            }
        }
        __syncthreads();

        // ==== dt-GEMM (K=16, 1-term) + fused gating, bc inline =============
        unsigned y_nonzero = 0u;
        {
            // bc[r] = dot(B,C): quad-parallel dot-16 + butterfly (rows fr, fr+8)
            const int jq = (lane & 3) * 4;
            float4 b0 = *(const float4*)&sh_dbl[fr * 48 + 16 + jq];
            float4 c0 = *(const float4*)&sh_dbl[fr * 48 + 32 + jq];
            float s0 = b0.x * c0.x + b0.y * c0.y + b0.z * c0.z + b0.w * c0.w;
            s0 += __shfl_xor_sync(0xffffffffu, s0, 1);
            s0 += __shfl_xor_sync(0xffffffffu, s0, 2);
            float4 b1 = *(const float4*)&sh_dbl[(fr + 8) * 48 + 16 + jq];
            float4 c1 = *(const float4*)&sh_dbl[(fr + 8) * 48 + 32 + jq];
            float s1 = b1.x * c1.x + b1.y * c1.y + b1.z * c1.z + b1.w * c1.w;
            s1 += __shfl_xor_sync(0xffffffffu, s1, 1);
            s1 += __shfl_xor_sync(0xffffffffu, s1, 2);
            const float bc0 = s0, bc1 = s1;

            const int wnt = wid * 4;    // 4 n-tiles per warp, 64 total
            unsigned aH[4];
            *(uint4*)aH = *(const uint4*)&dtH[lane * 4];

            #pragma unroll
            for (int j = 0; j < 4; j++) {
                int nt = wnt + j;
                float d[4] = {0.f, 0.f, 0.f, 0.f};
                uint2 W = g_W4h[((size_t)l * NT4 + nt) * 32 + lane];
                mma_bf16(d, aH, W.x, W.y);

                int c = nt * 8 + fc;
                float4 dbd = g_dbd[l * 256 + (c >> 1)];
                float dt00 = softplus_f(d[0] + dbd.x);
                float dt01 = softplus_f(d[1] + dbd.z);
                float dt10 = softplus_f(d[2] + dbd.x);
                float dt11 = softplus_f(d[3] + dbd.z);
                int idx = ((c >> 4) * 32 + lane) * 4 + 2 * (nt & 1);
                uint2 xhp = *(uint2*)&xH[idx];
                uint2 zhp = *(const uint2*)&zH[idx];
                float2 xc0 = bf2f2(xhp.x), sz0 = bf2f2(zhp.x);
                float2 xc1 = bf2f2(xhp.y), sz1 = bf2f2(zhp.y);
                float y00 = xc0.x * (dt00 * bc0 + dbd.y) * sz0.x;
                float y01 = xc0.y * (dt01 * bc0 + dbd.w) * sz0.y;
                float y10 = xc1.x * (dt10 * bc1 + dbd.y) * sz1.x;
                float y11 = xc1.y * (dt11 * bc1 + dbd.w) * sz1.y;
                unsigned p0 = pack_bf2(y00, y01);
                unsigned p1 = pack_bf2(y10, y11);
                *(uint2*)&xH[idx] = make_uint2(p0, p1);
                y_nonzero |= (p0 & 0x7FFF7FFFu) | (p1 & 0x7FFF7FFFu);
            }
        }
        // Exit (a): y == 0 (bf16) => h' = y @ out_proj = 0 for any weights.
        if (!__syncthreads_or(y_nonzero != 0u)) {
            for (int i = t; i < 2048; i += NTHREADS) hH[i] = 0u;
            __syncthreads();
            break;
        }

        // ==== GEMM3: h = y @ out_proj, 2 nt/warp, W double-buffer ==========
        unsigned h_nonzero = 0u;
        {
            float acc3[2][4];
            #pragma unroll
            for (int m = 0; m < 2; m++)
                #pragma unroll
                for (int j = 0; j < 4; j++) acc3[m][j] = 0.f;

            const int nt0 = wid * 2;
            const uint4* bwbase = g_W3 + ((size_t)l * (KT3 / 2) * NT3 + nt0) * 32 + lane;
            uint4 nW0 = bwbase[0];
            uint4 nW1 = bwbase[32];
            for (int ktp = 0; ktp < KT3 / 2; ktp++) {
                uint4 W0 = nW0, W1 = nW1;
                const int kn = (ktp + 1) & (KT3 / 2 - 1);
                nW0 = bwbase[(size_t)kn * NT3 * 32];
                nW1 = bwbase[(size_t)kn * NT3 * 32 + 32];
                const int k0 = 2 * ktp, k1 = k0 + 1;
                unsigned a0[4], a1[4];
                *(uint4*)a0 = *(const uint4*)&xH[(k0 * 32 + lane) * 4];
                *(uint4*)a1 = *(const uint4*)&xH[(k1 * 32 + lane) * 4];
                mma_bf16(acc3[0], a0, W0.x, W0.y);
                mma_bf16(acc3[1], a0, W1.x, W1.y);
                mma_bf16(acc3[0], a1, W0.z, W0.w);
                mma_bf16(acc3[1], a1, W1.z, W1.w);
            }
            // epilogue: h-frags + packed zero-detection
            #pragma unroll
            for (int m = 0; m < 2; m++) {
                int nt = nt0 + m;
                int c = nt * 8 + fc;
                int idx = ((c >> 4) * 32 + lane) * 4 + 2 * (nt & 1);
                unsigned p0 = pack_bf2(acc3[m][0], acc3[m][1]);
                unsigned p1 = pack_bf2(acc3[m][2], acc3[m][3]);
                *(uint2*)&hH[idx] = make_uint2(p0, p1);
                h_nonzero |= (p0 & 0x7FFF7FFFu) | (p1 & 0x7FFF7FFFu);
            }
        }
        // Exit (b): h == 0 (bf16) is an exact fixed point of the layer map.
        if (!__syncthreads_or(h_nonzero != 0u)) break;
    }

    // ---- output head: out = h @ Wo + bo (h reconstructed from frags) ----
    if (t < ROWS) {
        const int r = t;
        float s = 0.f;
        #pragma unroll 4
        for (int cp = 0; cp < 128; cp++) {
            int c = cp * 2;
            int idx = ((c >> 4) * 32 + (r & 7) * 4 + ((c & 7) >> 1)) * 4
                      + (r >> 3) + 2 * ((c >> 3) & 1);
            float2 vh = bf2f2(hH[idx]);
            float2 wv = *(const float2*)(Wo + c);
            s = fmaf(vh.x, wv.x, s);
            s = fmaf(vh.y, wv.y, s);
        }
        out[row0 + r] = s + bo[0];
    }
}

// ---------------------------------------------------------------------------
extern "C" void kernel_launch(void* const* d_in, const int* in_sizes, int n_in,
                              void* d_out, int out_size)
{
    (void)in_sizes; (void)n_in; (void)out_size;

    prep_kernel<<<(NG1 + NG3 + NG2 + NG4 + 2 * NCP + 255) / 256, 256>>>(
        (const float*)d_in[3],    // in_proj_w
        (const float*)d_in[11],   // out_proj_w
        (const float*)d_in[6],    // x_proj_w
        (const float*)d_in[7],    // dt_proj_w
        (const float*)d_in[4],    // conv_w
        (const float*)d_in[5],    // conv_b
        (const float*)d_in[8],    // dt_proj_b
        (const float*)d_in[10]);  // D

    const size_t smem_bytes = (size_t)11136 * 4;  // 44544 B/CTA

    cudaFuncSetAttribute(mamba_icl_kernel,
                         cudaFuncAttributeMaxDynamicSharedMemorySize,
                         (int)smem_bytes);

    mamba_icl_kernel<<<BATCH / ROWS, NTHREADS, smem_bytes>>>(
        (const float*)d_in[0],   // x
        (const float*)d_in[1],   // Wi
        (const float*)d_in[2],   // bi
        // d_in[9] = A_log dead (h0 = 0, L = 1)
        (const float*)d_in[12],  // Wo
        (const float*)d_in[13],  // bo
        (float*)d_out);
}

// round 17
// speedup vs baseline: 1.1510x; 1.1510x over previous
#include <cuda_runtime.h>
#include <cuda_bf16.h>
#include <math.h>

#define NLAYERS 12
#define DMODEL  256
#define DINNER  512
#define DTRANK  16
#define DSTATE  16
#define INDIM   230
#define BATCH   4096
#define ROWS    16
#define NTHREADS 512

#define KT1 16    // 256/16 k-tiles, GEMM1
#define NT1 128   // 1024/8 n-tiles, GEMM1
#define KT3 32    // 512/16 k-tiles, GEMM3
#define NT3 32    // 256/8  n-tiles, GEMM3
#define KT2 32    // 512/16 k-tiles, GEMM2
#define NT2 6     // 48/8   n-tiles, GEMM2
#define NT4 64    // 512/8  n-tiles, dt-GEMM (K=16)
// packed single-term weights:
//   g_W1: uint4 per (kt, nt-pair): .xy = nt even, .zw = nt odd
//   g_W3: uint4 per (kt-pair, nt): .xy = kt even, .zw = kt odd
#define NG1 (NLAYERS*KT1*(NT1/2)*32)   // 393216 uint4
#define NG3 (NLAYERS*(KT3/2)*NT3*32)   // 196608 uint4
#define NG2 (NLAYERS*KT2*NT2*32)       // 73728 uint2
#define NG4 (NLAYERS*NT4*32)           // 24576 uint2
#define NCP (NLAYERS*256)              // col pairs for aux packs

__device__ uint4  g_W1[NG1];
__device__ uint4  g_W3[NG3];
__device__ uint2  g_W2h[NG2];
__device__ uint2  g_W4h[NG4];
__device__ float4 g_cvb[NCP];   // (convw3[c], convb[c], convw3[c+1], convb[c+1])
__device__ float4 g_dbd[NCP];   // (dtb[c], D[c], dtb[c+1], D[c+1])

// ---------------------------------------------------------------------------
union F2 { float2 f; unsigned long long u; };
__device__ __forceinline__ void ffma2(F2 &d, const F2 a, const F2 b) {
    asm("fma.rn.f32x2 %0, %1, %2, %0;" : "+l"(d.u) : "l"(a.u), "l"(b.u));
}
__device__ __forceinline__ F2 bcast2(float v) { F2 r; r.f = make_float2(v, v); return r; }

// silu(v) = v * sigmoid(v) = v * (0.5 + 0.5*tanh(v/2))  — MUFU.TANH path
__device__ __forceinline__ float silu_f(float v) {
    float th;
    asm("tanh.approx.f32 %0, %1;" : "=f"(th) : "f"(v * 0.5f));
    return v * fmaf(0.5f, th, 0.5f);
}
// softplus(v) = ln2 * log2(1 + 2^(v*log2e)) — MUFU.EX2/LG2 path
__device__ __forceinline__ float softplus_f(float v) {
    if (v > 20.0f) return v;
    float e, lg;
    asm("ex2.approx.f32 %0, %1;" : "=f"(e)  : "f"(v * 1.44269504f));
    asm("lg2.approx.f32 %0, %1;" : "=f"(lg) : "f"(1.0f + e));
    return 0.69314718f * lg;
}

__device__ __forceinline__ unsigned pack_bf2(float x, float y) {
    __nv_bfloat162 h = __floats2bfloat162_rn(x, y);
    return *reinterpret_cast<unsigned*>(&h);
}
__device__ __forceinline__ float2 bf2f2(unsigned p) {
    __nv_bfloat162 b = *reinterpret_cast<__nv_bfloat162*>(&p);
    return __bfloat1622float2(b);
}

__device__ __forceinline__ void mma_bf16(float (&d)[4], const unsigned (&a)[4],
                                         unsigned b0, unsigned b1) {
    asm volatile(
        "mma.sync.aligned.m16n8k16.row.col.f32.bf16.bf16.f32 "
        "{%0,%1,%2,%3}, {%4,%5,%6,%7}, {%8,%9}, {%0,%1,%2,%3};"
        : "+f"(d[0]), "+f"(d[1]), "+f"(d[2]), "+f"(d[3])
        : "r"(a[0]), "r"(a[1]), "r"(a[2]), "r"(a[3]), "r"(b0), "r"(b1));
}

// ---------------------------------------------------------------------------
// prep: repack weights into mma B-fragment order (single-term bf16, packed)
// plus interleaved epilogue constants.
// ---------------------------------------------------------------------------
extern "C" __global__ void prep_kernel(const float* __restrict__ in_proj_w,
                                       const float* __restrict__ out_proj_w,
                                       const float* __restrict__ x_proj_w,
                                       const float* __restrict__ dt_proj_w,
                                       const float* __restrict__ conv_w,
                                       const float* __restrict__ conv_b,
                                       const float* __restrict__ dt_proj_b,
                                       const float* __restrict__ Dvec)
{
    int gid = blockIdx.x * blockDim.x + threadIdx.x;

    if (gid < NG1) {
        int idx = gid;
        int lane = idx & 31; int rest = idx >> 5;
        int ntp = rest % (NT1 / 2); rest /= (NT1 / 2);
        int kt = rest % KT1; int l = rest / KT1;
        int n0 = (2 * ntp) * 8 + (lane >> 2);
        int n1 = n0 + 8;
        int k0 = kt * 16 + (lane & 3) * 2;
        const float* W = in_proj_w + (size_t)l * DMODEL * 1024;
        g_W1[idx] = make_uint4(
            pack_bf2(W[(size_t)k0 * 1024 + n0],       W[(size_t)(k0 + 1) * 1024 + n0]),
            pack_bf2(W[(size_t)(k0 + 8) * 1024 + n0], W[(size_t)(k0 + 9) * 1024 + n0]),
            pack_bf2(W[(size_t)k0 * 1024 + n1],       W[(size_t)(k0 + 1) * 1024 + n1]),
            pack_bf2(W[(size_t)(k0 + 8) * 1024 + n1], W[(size_t)(k0 + 9) * 1024 + n1]));
    } else if (gid < NG1 + NG3) {
        int idx = gid - NG1;
        int lane = idx & 31; int rest = idx >> 5;
        int nt = rest % NT3; rest /= NT3;
        int ktp = rest % (KT3 / 2); int l = rest / (KT3 / 2);
        int n  = nt * 8 + (lane >> 2);
        int ka = (2 * ktp) * 16 + (lane & 3) * 2;
        int kb = ka + 16;
        const float* W = out_proj_w + (size_t)l * DINNER * DMODEL;
        g_W3[idx] = make_uint4(
            pack_bf2(W[(size_t)ka * DMODEL + n],       W[(size_t)(ka + 1) * DMODEL + n]),
            pack_bf2(W[(size_t)(ka + 8) * DMODEL + n], W[(size_t)(ka + 9) * DMODEL + n]),
            pack_bf2(W[(size_t)kb * DMODEL + n],       W[(size_t)(kb + 1) * DMODEL + n]),
            pack_bf2(W[(size_t)(kb + 8) * DMODEL + n], W[(size_t)(kb + 9) * DMODEL + n]));
    } else if (gid < NG1 + NG3 + NG2) {
        int idx = gid - NG1 - NG3;
        int lane = idx & 31; int rest = idx >> 5;
        int nt = rest % NT2; rest /= NT2;
        int kt = rest % KT2; int l = rest / KT2;
        int n  = nt * 8 + (lane >> 2);
        int k0 = kt * 16 + (lane & 3) * 2;
        const float* W = x_proj_w + (size_t)l * DINNER * 48;
        g_W2h[idx] = make_uint2(
            pack_bf2(W[(size_t)k0 * 48 + n],       W[(size_t)(k0 + 1) * 48 + n]),
            pack_bf2(W[(size_t)(k0 + 8) * 48 + n], W[(size_t)(k0 + 9) * 48 + n]));
    } else if (gid < NG1 + NG3 + NG2 + NG4) {
        int idx = gid - NG1 - NG3 - NG2;
        int lane = idx & 31; int rest = idx >> 5;
        int nt = rest % NT4; int l = rest / NT4;
        int n  = nt * 8 + (lane >> 2);
        int k0 = (lane & 3) * 2;
        const float* W = dt_proj_w + (size_t)l * DTRANK * DINNER;
        g_W4h[idx] = make_uint2(
            pack_bf2(W[(size_t)k0 * DINNER + n],       W[(size_t)(k0 + 1) * DINNER + n]),
            pack_bf2(W[(size_t)(k0 + 8) * DINNER + n], W[(size_t)(k0 + 9) * DINNER + n]));
    } else if (gid < NG1 + NG3 + NG2 + NG4 + NCP) {
        int idx = gid - NG1 - NG3 - NG2 - NG4;
        int cp = idx & 255, l = idx >> 8;
        int c = cp * 2;
        g_cvb[idx] = make_float4(conv_w[((size_t)l * DINNER + c) * 4 + 3],
                                 conv_b[(size_t)l * DINNER + c],
                                 conv_w[((size_t)l * DINNER + c + 1) * 4 + 3],
                                 conv_b[(size_t)l * DINNER + c + 1]);
    } else if (gid < NG1 + NG3 + NG2 + NG4 + 2 * NCP) {
        int idx = gid - NG1 - NG3 - NG2 - NG4 - NCP;
        int cp = idx & 255, l = idx >> 8;
        int c = cp * 2;
        g_dbd[idx] = make_float4(dt_proj_b[(size_t)l * DINNER + c],
                                 Dvec[(size_t)l * DINNER + c],
                                 dt_proj_b[(size_t)l * DINNER + c + 1],
                                 Dvec[(size_t)l * DINNER + c + 1]);
    }
}

// ---------------------------------------------------------------------------
// main: one block = 16 batch rows, 512 threads, 2 CTAs/SM.
// 4 phases/layer; W AND A-frag double-buffering; MUFU-approx silu/softplus.
// G2: 12 warps, kh-split (16-iter chains); dt partials packed directly into
// dtH0/dtH1 and summed in the gating phase (no extra barrier).
// THREE exact exits (h==0 fixed point; wall = max over CTAs):
//   (0) xc == 0 after GEMM1; (a) y == 0 after gating; (b) h' == 0 after GEMM3.
// A-frag layout: (row r, col pair c): kt=c/16, lane=(r%8)*4+((c%8)/2),
//   reg=(r/8)+2*((c%16)/8)
// SMEM (words): dbl[0,1536) | u32 at 1536: dtH0 128 | dtH1 128 | hH 2048 |
//   xH 4096 | zH 4096   -> 12032 words = 48128 B/CTA
// ---------------------------------------------------------------------------
extern "C" __global__ void __launch_bounds__(NTHREADS, 2)
mamba_icl_kernel(const float* __restrict__ x,
                 const float* __restrict__ Wi,
                 const float* __restrict__ bi,
                 const float* __restrict__ Wo,
                 const float* __restrict__ bo,
                 float* __restrict__ out)
{
    extern __shared__ float sm[];
    float*    sh_dbl = sm;                  // 2 x 16x48 (kh halves)
    unsigned* fr_    = (unsigned*)(sm + 1536);
    unsigned* dtH0 = fr_;                 // 128
    unsigned* dtH1 = fr_ + 128;           // 128
    unsigned* hH   = fr_ + 256;           // 2048
    unsigned* xH   = fr_ + 2304;          // 4096
    unsigned* zH   = fr_ + 6400;          // 4096

    const int t    = threadIdx.x;
    const int row0 = blockIdx.x * ROWS;
    const int wid  = t >> 5;          // 0..15
    const int lane = t & 31;
    const int fr   = lane >> 2;
    const int fc   = (lane & 3) * 2;

    // ---- stage x into scratch aliasing the xc-frag region ----
    float* sh_x = (float*)xH;   // 3680 floats < 4096-word xH region
    for (int idx = t; idx < ROWS * INDIM; idx += NTHREADS) {
        int r = idx / INDIM, c = idx - r * INDIM;
        sh_x[r * INDIM + c] = x[(size_t)(row0 + r) * INDIM + c];
    }
    __syncthreads();

    // ---- input projection -> h-frags (fp32 FFMA2, one-time) ----
    {
        const int tx = t & 127;     // col pair
        const int ty = t >> 7;      // 0..3 -> 4 rows each
        F2 acc[4];
        #pragma unroll
        for (int i = 0; i < 4; i++) acc[i].f = make_float2(0.f, 0.f);
        const int rbase = ty * 4;
        #pragma unroll 2
        for (int k0 = 0; k0 < INDIM; k0 += 2) {
            F2 w0; w0.f = *(const float2*)(Wi + (size_t)k0 * DMODEL + tx * 2);
            F2 w1; w1.f = *(const float2*)(Wi + (size_t)(k0 + 1) * DMODEL + tx * 2);
            #pragma unroll
            for (int i = 0; i < 4; i++) {
                float2 a2 = *(const float2*)(sh_x + (rbase + i) * INDIM + k0);
                ffma2(acc[i], bcast2(a2.x), w0);
                ffma2(acc[i], bcast2(a2.y), w1);
            }
        }
        __syncthreads();   // all reads of sh_x done before frag region reuse
        float2 bv = *(const float2*)(bi + tx * 2);
        const int kt = tx >> 3;
        #pragma unroll
        for (int i = 0; i < 4; i++) {
            int row = rbase + i;
            unsigned hh = pack_bf2(acc[i].f.x + bv.x, acc[i].f.y + bv.y);
            int idx = (kt * 32 + (row & 7) * 4 + (tx & 3)) * 4
                      + (row >> 3) + 2 * ((tx >> 2) & 1);
            hH[idx] = hh;
        }
    }
    __syncthreads();

    for (int l = 0; l < NLAYERS; l++) {
        // ==== GEMM1: 2 chunks x 4nt; W + A double-buffered =================
        unsigned xc_nonzero = 0u;
        #pragma unroll
        for (int ch = 0; ch < 2; ch++) {
            float acc[4][4];   // 16 regs
            #pragma unroll
            for (int j = 0; j < 4; j++)
                #pragma unroll
                for (int k = 0; k < 4; k++) acc[j][k] = 0.f;

            const int ntp0 = wid * 4 + ch * 2;
            const uint4* bwbase = g_W1 + ((size_t)l * KT1 * (NT1 / 2) + ntp0) * 32 + lane;
            uint4 nW0 = bwbase[0];
            uint4 nW1 = bwbase[32];
            unsigned nah[4];
            *(uint4*)nah = *(const uint4*)&hH[lane * 4];
            for (int kt = 0; kt < KT1; kt++) {
                uint4 W0 = nW0, W1 = nW1;
                unsigned ah[4];
                ah[0] = nah[0]; ah[1] = nah[1]; ah[2] = nah[2]; ah[3] = nah[3];
                const int kn = (kt + 1) & (KT1 - 1);   // wraps; extras discarded
                nW0 = bwbase[(size_t)kn * (NT1 / 2) * 32];
                nW1 = bwbase[(size_t)kn * (NT1 / 2) * 32 + 32];
                *(uint4*)nah = *(const uint4*)&hH[(kn * 32 + lane) * 4];
                mma_bf16(acc[0], ah, W0.x, W0.y);
                mma_bf16(acc[1], ah, W0.z, W0.w);
                mma_bf16(acc[2], ah, W1.x, W1.y);
                mma_bf16(acc[3], ah, W1.z, W1.w);
            }
            // epilogue: warps 0-7 -> xc frags (conv+silu); 8-15 -> z frags
            if (wid < 8) {
                #pragma unroll
                for (int j = 0; j < 4; j++) {
                    int nt = (wid * 4 + ch * 2) * 2 + j;
                    int c  = nt * 8 + fc;
                    float4 cv = g_cvb[l * 256 + (c >> 1)];
                    float v00 = silu_f(fmaf(acc[j][0], cv.x, cv.y));
                    float v01 = silu_f(fmaf(acc[j][1], cv.z, cv.w));
                    float v10 = silu_f(fmaf(acc[j][2], cv.x, cv.y));
                    float v11 = silu_f(fmaf(acc[j][3], cv.z, cv.w));
                    unsigned p0 = pack_bf2(v00, v01);
                    unsigned p1 = pack_bf2(v10, v11);
                    int idx = ((c >> 4) * 32 + lane) * 4 + 2 * (nt & 1);
                    *(uint2*)&xH[idx] = make_uint2(p0, p1);
                    xc_nonzero |= (p0 & 0x7FFF7FFFu) | (p1 & 0x7FFF7FFFu);
                }
            } else {
                #pragma unroll
                for (int j = 0; j < 4; j++) {
                    int nt = ((wid - 8) * 4 + ch * 2) * 2 + j;   // z tile 0..63
                    int c  = nt * 8 + fc;
                    int idx = ((c >> 4) * 32 + lane) * 4 + 2 * (nt & 1);
                    *(uint2*)&zH[idx] = make_uint2(
                        pack_bf2(silu_f(acc[j][0]), silu_f(acc[j][1])),
                        pack_bf2(silu_f(acc[j][2]), silu_f(acc[j][3])));
                }
            }
        }
        // Exit (0): xc == 0 (bf16) => y = xc*(...)*(...) = 0 => h' = 0.
        if (!__syncthreads_or(xc_nonzero != 0u)) {
            for (int i = t; i < 2048; i += NTHREADS) hH[i] = 0u;
            __syncthreads();
            break;
        }

        // ==== GEMM2: 12 warps (2kh x 6nt), 16-iter chains, W prefetch ======
        // nt2 0,1 own dt columns 0-15: partial D-frags packed straight into
        // dtH0/dtH1 (summed in gating; no extra phase).
        if (wid < 12) {
            const int kh  = wid / 6;
            const int nt2 = wid % 6;
            const int ktb = kh * 16;
            float d[4] = {0.f, 0.f, 0.f, 0.f};
            const uint2* w2base = g_W2h + ((size_t)(l * KT2 + ktb) * NT2 + nt2) * 32 + lane;
            uint2 nW = w2base[0];
            for (int kk = 0; kk < 16; kk++) {
                uint2 W = nW;
                const int knn = (kk + 1) & 15;
                nW = w2base[(size_t)knn * NT2 * 32];
                unsigned ahi[4];
                *(uint4*)ahi = *(const uint4*)&xH[((ktb + kk) * 32 + lane) * 4];
                mma_bf16(d, ahi, W.x, W.y);
            }
            if (nt2 < 2) {
                unsigned* dst = kh ? dtH1 : dtH0;
                dst[lane * 4 + 2 * nt2]     = pack_bf2(d[0], d[1]);
                dst[lane * 4 + 2 * nt2 + 1] = pack_bf2(d[2], d[3]);
            } else {
                float* dbl = sh_dbl + kh * 768;
                int c = nt2 * 8 + fc;
                *(float2*)&dbl[fr * 48 + c]       = make_float2(d[0], d[1]);
                *(float2*)&dbl[(fr + 8) * 48 + c] = make_float2(d[2], d[3]);
            }
        }
        __syncthreads();

        // ==== dt-GEMM (K=16, 1-term) + fused gating, bc inline =============
        unsigned y_nonzero = 0u;
        {
            // bc[r] = dot(B,C) with kh-partials summed; quad dot-16 + butterfly
            const int jq = (lane & 3) * 4;
            float4 bA0 = *(const float4*)&sh_dbl[fr * 48 + 16 + jq];
            float4 bB0 = *(const float4*)&sh_dbl[768 + fr * 48 + 16 + jq];
            float4 cA0 = *(const float4*)&sh_dbl[fr * 48 + 32 + jq];
            float4 cB0 = *(const float4*)&sh_dbl[768 + fr * 48 + 32 + jq];
            float s0 = (bA0.x + bB0.x) * (cA0.x + cB0.x)
                     + (bA0.y + bB0.y) * (cA0.y + cB0.y)
                     + (bA0.z + bB0.z) * (cA0.z + cB0.z)
                     + (bA0.w + bB0.w) * (cA0.w + cB0.w);
            s0 += __shfl_xor_sync(0xffffffffu, s0, 1);
            s0 += __shfl_xor_sync(0xffffffffu, s0, 2);
            float4 bA1 = *(const float4*)&sh_dbl[(fr + 8) * 48 + 16 + jq];
            float4 bB1 = *(const float4*)&sh_dbl[768 + (fr + 8) * 48 + 16 + jq];
            float4 cA1 = *(const float4*)&sh_dbl[(fr + 8) * 48 + 32 + jq];
            float4 cB1 = *(const float4*)&sh_dbl[768 + (fr + 8) * 48 + 32 + jq];
            float s1 = (bA1.x + bB1.x) * (cA1.x + cB1.x)
                     + (bA1.y + bB1.y) * (cA1.y + cB1.y)
                     + (bA1.z + bB1.z) * (cA1.z + cB1.z)
                     + (bA1.w + bB1.w) * (cA1.w + cB1.w);
            s1 += __shfl_xor_sync(0xffffffffu, s1, 1);
            s1 += __shfl_xor_sync(0xffffffffu, s1, 2);
            const float bc0 = s0, bc1 = s1;

            // dt A-fragments: sum the two kh partials
            uint4 pa = *(const uint4*)&dtH0[lane * 4];
            uint4 pb = *(const uint4*)&dtH1[lane * 4];
            unsigned aH[4];
            {
                float2 fa, fb;
                fa = bf2f2(pa.x); fb = bf2f2(pb.x); aH[0] = pack_bf2(fa.x + fb.x, fa.y + fb.y);
                fa = bf2f2(pa.y); fb = bf2f2(pb.y); aH[1] = pack_bf2(fa.x + fb.x, fa.y + fb.y);
                fa = bf2f2(pa.z); fb = bf2f2(pb.z); aH[2] = pack_bf2(fa.x + fb.x, fa.y + fb.y);
                fa = bf2f2(pa.w); fb = bf2f2(pb.w); aH[3] = pack_bf2(fa.x + fb.x, fa.y + fb.y);
            }

            const int wnt = wid * 4;    // 4 n-tiles per warp, 64 total
            #pragma unroll
            for (int j = 0; j < 4; j++) {
                int nt = wnt + j;
                float d[4] = {0.f, 0.f, 0.f, 0.f};
                uint2 W = g_W4h[((size_t)l * NT4 + nt) * 32 + lane];
                mma_bf16(d, aH, W.x, W.y);

                int c = nt * 8 + fc;
                float4 dbd = g_dbd[l * 256 + (c >> 1)];
                float dt00 = softplus_f(d[0] + dbd.x);
                float dt01 = softplus_f(d[1] + dbd.z);
                float dt10 = softplus_f(d[2] + dbd.x);
                float dt11 = softplus_f(d[3] + dbd.z);
                int idx = ((c >> 4) * 32 + lane) * 4 + 2 * (nt & 1);
                uint2 xhp = *(uint2*)&xH[idx];
                uint2 zhp = *(const uint2*)&zH[idx];
                float2 xc0 = bf2f2(xhp.x), sz0 = bf2f2(zhp.x);
                float2 xc1 = bf2f2(xhp.y), sz1 = bf2f2(zhp.y);
                float y00 = xc0.x * fmaf(dt00, bc0, dbd.y) * sz0.x;
                float y01 = xc0.y * fmaf(dt01, bc0, dbd.w) * sz0.y;
                float y10 = xc1.x * fmaf(dt10, bc1, dbd.y) * sz1.x;
                float y11 = xc1.y * fmaf(dt11, bc1, dbd.w) * sz1.y;
                unsigned p0 = pack_bf2(y00, y01);
                unsigned p1 = pack_bf2(y10, y11);
                *(uint2*)&xH[idx] = make_uint2(p0, p1);
                y_nonzero |= (p0 & 0x7FFF7FFFu) | (p1 & 0x7FFF7FFFu);
            }
        }
        // Exit (a): y == 0 (bf16) => h' = y @ out_proj = 0 for any weights.
        if (!__syncthreads_or(y_nonzero != 0u)) {
            for (int i = t; i < 2048; i += NTHREADS) hH[i] = 0u;
            __syncthreads();
            break;
        }

        // ==== GEMM3: 2 nt/warp; W + A double-buffered ======================
        unsigned h_nonzero = 0u;
        {
            float acc3[2][4];
            #pragma unroll
            for (int m = 0; m < 2; m++)
                #pragma unroll
                for (int j = 0; j < 4; j++) acc3[m][j] = 0.f;

            const int nt0 = wid * 2;
            const uint4* bwbase = g_W3 + ((size_t)l * (KT3 / 2) * NT3 + nt0) * 32 + lane;
            uint4 nW0 = bwbase[0];
            uint4 nW1 = bwbase[32];
            unsigned na0[4], na1[4];
            *(uint4*)na0 = *(const uint4*)&xH[lane * 4];
            *(uint4*)na1 = *(const uint4*)&xH[(32 + lane) * 4];
            for (int ktp = 0; ktp < KT3 / 2; ktp++) {
                uint4 W0 = nW0, W1 = nW1;
                unsigned a0[4], a1[4];
                a0[0] = na0[0]; a0[1] = na0[1]; a0[2] = na0[2]; a0[3] = na0[3];
                a1[0] = na1[0]; a1[1] = na1[1]; a1[2] = na1[2]; a1[3] = na1[3];
                const int kn = (ktp + 1) & (KT3 / 2 - 1);
                nW0 = bwbase[(size_t)kn * NT3 * 32];
                nW1 = bwbase[(size_t)kn * NT3 * 32 + 32];
                *(uint4*)na0 = *(const uint4*)&xH[(2 * kn * 32 + lane) * 4];
                *(uint4*)na1 = *(const uint4*)&xH[((2 * kn + 1) * 32 + lane) * 4];
                mma_bf16(acc3[0], a0, W0.x, W0.y);
                mma_bf16(acc3[1], a0, W1.x, W1.y);
                mma_bf16(acc3[0], a1, W0.z, W0.w);
                mma_bf16(acc3[1], a1, W1.z, W1.w);
            }
            // epilogue: h-frags + packed zero-detection
            #pragma unroll
            for (int m = 0; m < 2; m++) {
                int nt = nt0 + m;
                int c = nt * 8 + fc;
                int idx = ((c >> 4) * 32 + lane) * 4 + 2 * (nt & 1);
                unsigned p0 = pack_bf2(acc3[m][0], acc3[m][1]);
                unsigned p1 = pack_bf2(acc3[m][2], acc3[m][3]);
                *(uint2*)&hH[idx] = make_uint2(p0, p1);
                h_nonzero |= (p0 & 0x7FFF7FFFu) | (p1 & 0x7FFF7FFFu);
            }
        }
        // Exit (b): h == 0 (bf16) is an exact fixed point of the layer map.
        if (!__syncthreads_or(h_nonzero != 0u)) break;
    }

    // ---- output head: out = h @ Wo + bo (h reconstructed from frags) ----
    if (t < ROWS) {
        const int r = t;
        float s = 0.f;
        #pragma unroll 4
        for (int cp = 0; cp < 128; cp++) {
            int c = cp * 2;
            int idx = ((c >> 4) * 32 + (r & 7) * 4 + ((c & 7) >> 1)) * 4
                      + (r >> 3) + 2 * ((c >> 3) & 1);
            float2 vh = bf2f2(hH[idx]);
            float2 wv = *(const float2*)(Wo + c);
            s = fmaf(vh.x, wv.x, s);
            s = fmaf(vh.y, wv.y, s);
        }
        out[row0 + r] = s + bo[0];
    }
}

// ---------------------------------------------------------------------------
extern "C" void kernel_launch(void* const* d_in, const int* in_sizes, int n_in,
                              void* d_out, int out_size)
{
    (void)in_sizes; (void)n_in; (void)out_size;

    prep_kernel<<<(NG1 + NG3 + NG2 + NG4 + 2 * NCP + 255) / 256, 256>>>(
        (const float*)d_in[3],    // in_proj_w
        (const float*)d_in[11],   // out_proj_w
        (const float*)d_in[6],    // x_proj_w
        (const float*)d_in[7],    // dt_proj_w
        (const float*)d_in[4],    // conv_w
        (const float*)d_in[5],    // conv_b
        (const float*)d_in[8],    // dt_proj_b
        (const float*)d_in[10]);  // D

    const size_t smem_bytes = (size_t)12032 * 4;  // 48128 B/CTA

    cudaFuncSetAttribute(mamba_icl_kernel,
                         cudaFuncAttributeMaxDynamicSharedMemorySize,
                         (int)smem_bytes);

    mamba_icl_kernel<<<BATCH / ROWS, NTHREADS, smem_bytes>>>(
        (const float*)d_in[0],   // x
        (const float*)d_in[1],   // Wi
        (const float*)d_in[2],   // bi
        // d_in[9] = A_log dead (h0 = 0, L = 1)
        (const float*)d_in[12],  // Wo
        (const float*)d_in[13],  // bo
        (float*)d_out);
}